// round 3
// baseline (speedup 1.0000x reference)
#include <cuda_runtime.h>
#include <math.h>

#define B_      8
#define K_      256
#define DIM_    50257
#define PAD_    50264              // DIM_ rounded up to mult of 4, room for shift 0..3
#define KNN_    8
#define NCLASS_ 4
#define SCALE_  (-1.0f / (0.05f * (float)DIM_))

typedef unsigned long long u64;

// Scratch: 4 phase-shifted copies of log(logits). Copy p stores element d at
// physical index d+p, so loads of ll[d] are 16B-aligned when (d+p) % 4 == 0 —
// the same condition as qa rows whose start offset ≡ p (mod 4).
__device__ float g_ll4[4][B_][PAD_];     // ~6.4 MB
__device__ float g_sd[B_ * K_];

// ---------------------------------------------------------------------------
// Packed f32x2 helpers (sm_103a)
// ---------------------------------------------------------------------------
__device__ __forceinline__ u64 pk(float lo, float hi) {
    u64 r; asm("mov.b64 %0, {%1, %2};" : "=l"(r) : "f"(lo), "f"(hi)); return r;
}
__device__ __forceinline__ u64 bcast(float c) {
    unsigned u = __float_as_uint(c); return ((u64)u << 32) | (u64)u;
}
__device__ __forceinline__ void unpk(u64 v, float& lo, float& hi) {
    asm("mov.b64 {%0, %1}, %2;" : "=f"(lo), "=f"(hi) : "l"(v));
}
__device__ __forceinline__ u64 fma2(u64 a, u64 b, u64 c) {
    u64 d; asm("fma.rn.f32x2 %0, %1, %2, %3;" : "=l"(d) : "l"(a), "l"(b), "l"(c)); return d;
}
__device__ __forceinline__ u64 mul2(u64 a, u64 b) {
    u64 d; asm("mul.rn.f32x2 %0, %1, %2;" : "=l"(d) : "l"(a), "l"(b)); return d;
}
__device__ __forceinline__ u64 add2(u64 a, u64 b) {
    u64 d; asm("add.rn.f32x2 %0, %1, %2;" : "=l"(d) : "l"(a), "l"(b)); return d;
}

// ---------------------------------------------------------------------------
// Kernel 1: accurate log of logits, fanned out to the 4 shifted copies.
// grid = (ceil(DIM/256), B)
// ---------------------------------------------------------------------------
__global__ void k_log(const float* __restrict__ logits) {
    const int b = blockIdx.y;
    const int d = blockIdx.x * blockDim.x + threadIdx.x;
    if (d < DIM_) {
        float v = logf(logits[b * DIM_ + d]);
        #pragma unroll
        for (int p = 0; p < 4; p++) g_ll4[p][b][d + p] = v;
    }
}

// ---------------------------------------------------------------------------
// Fast log, x in [1e-3, 1]: centered exponent extract + deg-8 log1p Taylor.
// Scalar version (prologue/epilogue) and packed-pair version (main loop).
// ---------------------------------------------------------------------------
__device__ __forceinline__ float fastlog_s(float x) {
    int ix = __float_as_int(x);
    int kk = (ix - 0x3f350000) >> 23;
    float m = __int_as_float(ix - (kk << 23));
    float t = m - 1.0f;
    float z = t * t;
    float p = -0.125f;
    p = fmaf(p, t,  0.14285714f);
    p = fmaf(p, t, -0.16666667f);
    p = fmaf(p, t,  0.2f);
    p = fmaf(p, t, -0.25f);
    p = fmaf(p, t,  0.33333333f);
    float y = fmaf(t * z, p, fmaf(-0.5f, z, t));
    return fmaf((float)kk, 0.69314718f, y);
}

__device__ __forceinline__ u64 plog(float x0, float x1) {
    int i0 = __float_as_int(x0), i1 = __float_as_int(x1);
    int e0 = (i0 - 0x3f350000) >> 23;
    int e1 = (i1 - 0x3f350000) >> 23;
    float m0 = __int_as_float(i0 - (e0 << 23));   // [0.707, 1.414)
    float m1 = __int_as_float(i1 - (e1 << 23));
    u64 e = pk((float)e0, (float)e1);
    u64 t = add2(pk(m0, m1), bcast(-1.0f));       // [-0.293, 0.414]
    u64 z = mul2(t, t);
    u64 p = bcast(-0.125f);
    p = fma2(p, t, bcast( 0.14285714f));
    p = fma2(p, t, bcast(-0.16666667f));
    p = fma2(p, t, bcast( 0.2f));
    p = fma2(p, t, bcast(-0.25f));
    p = fma2(p, t, bcast( 0.33333333f));
    u64 y = fma2(mul2(t, z), p, fma2(bcast(-0.5f), z, t));
    return fma2(e, bcast(0.69314718f), y);
}

// ---------------------------------------------------------------------------
// Kernel 2: one block handles rows (b,k0) and (b,k0+4) — same 16B phase since
// 4*DIM ≡ 0 (mod 4). All three streams use aligned LDG.128.
// grid = B*K/2, 256 threads.
// ---------------------------------------------------------------------------
__global__ void __launch_bounds__(256) k_dist(const float* __restrict__ qa) {
    const int tid  = threadIdx.x;
    const int pidx = blockIdx.x;            // 0 .. 1023
    const int b    = pidx >> 7;
    const int r    = pidx & 127;
    const int k0   = ((r >> 2) << 3) + (r & 3);   // pairs (k0, k0+4) cover all k
    const int phi  = r & 3;                 // = k0 & 3 = row phase (b*256 ≡ 0 mod 4)

    const float* __restrict__ q0 = qa + (size_t)(b * K_ + k0) * DIM_;
    const float* __restrict__ q1 = q0 + 4 * (size_t)DIM_;
    const float* __restrict__ lb = &g_ll4[phi][b][phi];   // lb[d] == log(logits[b][d])

    const int d0   = (4 - phi) & 3;         // first 16B-aligned d
    const int nvec = (DIM_ - d0) >> 2;
    const int rem  = (DIM_ - d0) & 3;
    const int dend = d0 + (nvec << 2);

    float sa = 0.0f, sc = 0.0f;             // scalar partials (prologue/epilogue)
    if (tid < d0) {
        int d = tid;
        float l = lb[d], x0 = q0[d], x1 = q1[d];
        sa = x0 * (fastlog_s(x0) - l);
        sc = x1 * (fastlog_s(x1) - l);
    }
    if (tid < rem) {
        int d = dend + tid;
        float l = lb[d], x0 = q0[d], x1 = q1[d];
        sa += x0 * (fastlog_s(x0) - l);
        sc += x1 * (fastlog_s(x1) - l);
    }

    const float4* __restrict__ q0v = (const float4*)(q0 + d0);
    const float4* __restrict__ q1v = (const float4*)(q1 + d0);
    const float4* __restrict__ llv = (const float4*)(lb + d0);

    const u64 NEG1 = bcast(-1.0f);
    u64 aA0 = 0ull, aA1 = 0ull, aC0 = 0ull, aC1 = 0ull;

    #pragma unroll 2
    for (int t = tid; t < nvec; t += 256) {
        float4 a = __ldg(q0v + t);
        float4 c = __ldg(q1v + t);
        float4 l = __ldg(llv + t);
        // within-row pairs: pk sources are adjacent vector-load registers
        u64 la = pk(l.x, l.y), lbp = pk(l.z, l.w);
        aA0 = fma2(pk(a.x, a.y), fma2(la,  NEG1, plog(a.x, a.y)), aA0);
        aA1 = fma2(pk(a.z, a.w), fma2(lbp, NEG1, plog(a.z, a.w)), aA1);
        aC0 = fma2(pk(c.x, c.y), fma2(la,  NEG1, plog(c.x, c.y)), aC0);
        aC1 = fma2(pk(c.z, c.w), fma2(lbp, NEG1, plog(c.z, c.w)), aC1);
    }

    float fa0, fa1, fc0, fc1;
    unpk(add2(aA0, aA1), fa0, fa1);
    unpk(add2(aC0, aC1), fc0, fc1);
    float a0 = fa0 + fa1 + sa;
    float a1 = fc0 + fc1 + sc;

    #pragma unroll
    for (int s = 16; s > 0; s >>= 1) {
        a0 += __shfl_xor_sync(0xFFFFFFFFu, a0, s);
        a1 += __shfl_xor_sync(0xFFFFFFFFu, a1, s);
    }
    __shared__ float s0[8], s1[8];
    const int wid = tid >> 5;
    const int lid = tid & 31;
    if (lid == 0) { s0[wid] = a0; s1[wid] = a1; }
    __syncthreads();
    if (tid == 0) {
        float t0 = 0.0f, t1 = 0.0f;
        #pragma unroll
        for (int w = 0; w < 8; w++) { t0 += s0[w]; t1 += s1[w]; }
        g_sd[b * K_ + k0]     = t0 * SCALE_;
        g_sd[b * K_ + k0 + 4] = t1 * SCALE_;
    }
}

// ---------------------------------------------------------------------------
// Kernel 3: one block, warp w = batch b. Warp-shuffle top-8 with jax
// tie-breaking (lowest index wins), softmax, class scatter.
// ---------------------------------------------------------------------------
__global__ void __launch_bounds__(256) k_topk(const int* __restrict__ qlabel,
                                              float* __restrict__ out) {
    const int w    = threadIdx.x >> 5;
    const int lane = threadIdx.x & 31;

    float v[8];
    #pragma unroll
    for (int j = 0; j < 8; j++) v[j] = g_sd[w * K_ + j * 32 + lane];

    float topv[KNN_];
    int   topi[KNN_];
    #pragma unroll
    for (int r = 0; r < KNN_; r++) {
        float bv = -INFINITY; int bi = K_;
        #pragma unroll
        for (int j = 0; j < 8; j++) {
            int idx = j * 32 + lane;
            if (v[j] > bv) { bv = v[j]; bi = idx; }
        }
        #pragma unroll
        for (int s = 16; s > 0; s >>= 1) {
            float ov = __shfl_xor_sync(0xFFFFFFFFu, bv, s);
            int   oi = __shfl_xor_sync(0xFFFFFFFFu, bi, s);
            if (ov > bv || (ov == bv && oi < bi)) { bv = ov; bi = oi; }
        }
        topv[r] = bv; topi[r] = bi;
        if ((bi & 31) == lane) v[bi >> 5] = -INFINITY;
    }

    if (lane == 0) {
        float mx = topv[0];
        float wt[KNN_], sum = 0.0f;
        #pragma unroll
        for (int r = 0; r < KNN_; r++) { wt[r] = expf(topv[r] - mx); sum += wt[r]; }
        float inv = 1.0f / sum;
        float o[NCLASS_] = {0.0f, 0.0f, 0.0f, 0.0f};
        #pragma unroll
        for (int r = 0; r < KNN_; r++)
            o[qlabel[w * K_ + topi[r]]] += wt[r] * inv;
        #pragma unroll
        for (int c = 0; c < NCLASS_; c++) out[w * NCLASS_ + c] = o[c];
    }
}

// ---------------------------------------------------------------------------
// Launch
// ---------------------------------------------------------------------------
extern "C" void kernel_launch(void* const* d_in, const int* in_sizes, int n_in,
                              void* d_out, int out_size) {
    const float* logits = nullptr;
    const float* qa     = nullptr;
    const int*   qlabel = nullptr;
    for (int i = 0; i < n_in; i++) {
        if (in_sizes[i] == B_ * DIM_)           logits = (const float*)d_in[i];
        else if (in_sizes[i] == B_ * K_ * DIM_) qa     = (const float*)d_in[i];
        else if (in_sizes[i] == B_ * K_)        qlabel = (const int*)d_in[i];
    }
    float* out = (float*)d_out;

    dim3 lg((DIM_ + 255) / 256, B_);
    k_log <<<lg, 256>>>(logits);
    k_dist<<<B_ * K_ / 2, 256>>>(qa);
    k_topk<<<1, 256>>>(qlabel, out);
}